// round 3
// baseline (speedup 1.0000x reference)
#include <cuda_runtime.h>
#include <cstdint>

#define BB   64
#define TT   1024
#define II   64
#define HH   512
#define GG   1536
#define MM   (BB*TT)
#define NBG  4
#define BPG  16
#define NHS  32
#define HPS  16
#define NCTA (NBG*NHS)
#define RS   514   // padded smem row stride (floats)

__device__ float g_xg[(size_t)MM * GG];
__device__ float g_y [(size_t)MM * HH];
__device__ float g_h [2][BB * HH];
__device__ unsigned g_bar;

__device__ __forceinline__ void ffma2(float2 &d, const float2 a, const float2 b) {
    asm("{\n\t.reg .b64 ra, rb, rd;\n\t"
        "mov.b64 ra, {%2, %3};\n\t"
        "mov.b64 rb, {%4, %5};\n\t"
        "mov.b64 rd, {%0, %1};\n\t"
        "fma.rn.f32x2 rd, ra, rb, rd;\n\t"
        "mov.b64 {%0, %1}, rd;\n\t}"
        : "+f"(d.x), "+f"(d.y)
        : "f"(a.x), "f"(a.y), "f"(b.x), "f"(b.y));
}

__global__ void k_zero() {
    int i = blockIdx.x * blockDim.x + threadIdx.x;
    if (i == 0) g_bar = 0u;
    float* p = &g_h[0][0];
    for (int idx = i; idx < 2 * BB * HH; idx += gridDim.x * blockDim.x)
        p[idx] = 0.0f;
}

// C[M,N] = A[M,K] @ W[N,K]^T + bias ; 256 threads, 16x16 thread grid
template <int BM, int BN, int BK, int TM, int TN>
__global__ __launch_bounds__(256)
void sgemm_bias(const float* __restrict__ A, const float* __restrict__ W,
                const float* __restrict__ bias, float* __restrict__ C,
                int M, int N, int K)
{
    __shared__ float As[BK][BM];
    __shared__ float Ws[BK][BN];
    const int tid = threadIdx.x;
    const int c = tid & 15, r = tid >> 4;
    const int m0 = blockIdx.y * BM, n0 = blockIdx.x * BN;

    float acc[TM][TN];
#pragma unroll
    for (int i = 0; i < TM; i++)
#pragma unroll
        for (int j = 0; j < TN; j++) acc[i][j] = 0.f;

    for (int k0 = 0; k0 < K; k0 += BK) {
        for (int i = tid; i < BM * BK / 4; i += 256) {
            int am = i / (BK / 4), ak = (i % (BK / 4)) * 4;
            float4 v = *reinterpret_cast<const float4*>(&A[(size_t)(m0 + am) * K + k0 + ak]);
            As[ak][am] = v.x; As[ak + 1][am] = v.y; As[ak + 2][am] = v.z; As[ak + 3][am] = v.w;
        }
        for (int i = tid; i < BN * BK / 4; i += 256) {
            int wn = i / (BK / 4), wk = (i % (BK / 4)) * 4;
            float4 v = *reinterpret_cast<const float4*>(&W[(size_t)(n0 + wn) * K + k0 + wk]);
            Ws[wk][wn] = v.x; Ws[wk + 1][wn] = v.y; Ws[wk + 2][wn] = v.z; Ws[wk + 3][wn] = v.w;
        }
        __syncthreads();
#pragma unroll
        for (int kk = 0; kk < BK; kk++) {
            float a[TM], b[TN];
#pragma unroll
            for (int i = 0; i < TM; i++) a[i] = As[kk][r + 16 * i];
#pragma unroll
            for (int j = 0; j < TN; j++) b[j] = Ws[kk][c + 16 * j];
#pragma unroll
            for (int i = 0; i < TM; i++)
#pragma unroll
                for (int j = 0; j < TN; j++) acc[i][j] = fmaf(a[i], b[j], acc[i][j]);
        }
        __syncthreads();
    }
#pragma unroll
    for (int i = 0; i < TM; i++) {
        int m = m0 + r + 16 * i;
#pragma unroll
        for (int j = 0; j < TN; j++) {
            int n = n0 + c + 16 * j;
            C[(size_t)m * N + n] = acc[i][j] + bias[n];
        }
    }
}

// Persistent GRU scan: 128 CTAs x 256 thr. Thread (jl,bl) owns hidden jg, batch bglob.
__global__ __launch_bounds__(256, 1)
void gru_scan(const float* __restrict__ w_hh, const float* __restrict__ b_hh)
{
    extern __shared__ float sm[];
    float* ws = sm;               // 48 rows x RS (w_hh slice)
    float* hs = sm + 48 * RS;     // 16 rows x RS (staged h)

    const int tid  = threadIdx.x;
    const int hsid = blockIdx.x & (NHS - 1);
    const int bg   = blockIdx.x >> 5;
    const int jl = tid >> 4, bl = tid & 15;
    const int jg = hsid * HPS + jl;
    const int bglob = bg * BPG + bl;
    const unsigned nblocks = gridDim.x;

    for (int idx = tid; idx < 48 * HH; idx += 256) {
        int row = idx >> 9, k = idx & (HH - 1);
        int jj = row / 3, g = row % 3;
        ws[row * RS + k] = w_hh[((size_t)g * HH + hsid * HPS + jj) * HH + k];
    }
    const float br = b_hh[jg], bz = b_hh[HH + jg], bn = b_hh[2 * HH + jg];
    __syncthreads();

    const float2* w0 = reinterpret_cast<const float2*>(ws + (jl * 3 + 0) * RS);
    const float2* w1 = reinterpret_cast<const float2*>(ws + (jl * 3 + 1) * RS);
    const float2* w2 = reinterpret_cast<const float2*>(ws + (jl * 3 + 2) * RS);
    const float2* h2row = reinterpret_cast<const float2*>(hs + bl * RS);

    for (int t = 0; t < TT; t++) {
        const float* hsrc = g_h[t & 1];
        for (int i = tid; i < BPG * (HH / 4); i += 256) {
            int row = i >> 7, k4 = (i & 127) * 4;
            float4 v = __ldcg(reinterpret_cast<const float4*>(
                hsrc + (size_t)(bg * BPG + row) * HH + k4));
            float* dst = hs + row * RS + k4;
            dst[0] = v.x; dst[1] = v.y; dst[2] = v.z; dst[3] = v.w;
        }
        size_t mrow = ((size_t)bglob * TT + t) * GG;
        float xr = __ldg(&g_xg[mrow + jg]);
        float xz = __ldg(&g_xg[mrow + HH + jg]);
        float xn = __ldg(&g_xg[mrow + 2 * HH + jg]);
        __syncthreads();

        float hold = hs[bl * RS + jg];
        float2 ar = make_float2(br, 0.f), az = make_float2(bz, 0.f), an = make_float2(bn, 0.f);
#pragma unroll 8
        for (int k2 = 0; k2 < HH / 2; k2++) {
            float2 h2 = h2row[k2];
            ffma2(ar, h2, w0[k2]);
            ffma2(az, h2, w1[k2]);
            ffma2(an, h2, w2[k2]);
        }
        float rg = 1.f / (1.f + __expf(-(xr + ar.x + ar.y)));
        float zg = 1.f / (1.f + __expf(-(xz + az.x + az.y)));
        float ng = tanhf(xn + rg * (an.x + an.y));
        float hnew = (1.f - zg) * ng + zg * hold;

        __stcg(&g_h[(t + 1) & 1][bglob * HH + jg], hnew);
        g_y[((size_t)bglob * TT + t) * HH + jg] = hnew;

        __threadfence();
        __syncthreads();
        if (tid == 0) {
            unsigned target = (unsigned)(t + 1) * nblocks;
            atomicAdd(&g_bar, 1u);
            while (*(volatile unsigned*)&g_bar < target) { __nanosleep(32); }
        }
        __syncthreads();
    }
}

extern "C" void kernel_launch(void* const* d_in, const int* in_sizes, int n_in,
                              void* d_out, int out_size)
{
    const float* x    = (const float*)d_in[0];
    const float* wih0 = (const float*)d_in[1];
    const float* whh0 = (const float*)d_in[2];
    const float* bih0 = (const float*)d_in[3];
    const float* bhh0 = (const float*)d_in[4];
    const float* wih1 = (const float*)d_in[5];
    const float* whh1 = (const float*)d_in[6];
    const float* bih1 = (const float*)d_in[7];
    const float* bhh1 = (const float*)d_in[8];
    const float* fcw  = (const float*)d_in[9];
    const float* fcb  = (const float*)d_in[10];
    float* out = (float*)d_out;
    (void)in_sizes; (void)n_in; (void)out_size;

    float *xg, *y;
    cudaGetSymbolAddress((void**)&xg, g_xg);
    cudaGetSymbolAddress((void**)&y,  g_y);

    const int scan_smem = 64 * RS * 4;  // 131584 B
    static bool attr_set = false;
    if (!attr_set) {
        cudaFuncSetAttribute(gru_scan, cudaFuncAttributeMaxDynamicSharedMemorySize, scan_smem);
        attr_set = true;
    }

    dim3 gxg(GG / 128, MM / 128);

    // layer 0
    sgemm_bias<128,128,16,8,8><<<gxg, 256>>>(x, wih0, bih0, xg, MM, GG, II);
    k_zero<<<64, 256>>>();
    gru_scan<<<NCTA, 256, scan_smem>>>(whh0, bhh0);

    // layer 1
    sgemm_bias<128,128,16,8,8><<<gxg, 256>>>(y, wih1, bih1, xg, MM, GG, HH);
    k_zero<<<64, 256>>>();
    gru_scan<<<NCTA, 256, scan_smem>>>(whh1, bhh1);

    // output FC: [M, 64] = y @ fc_w^T + fc_b
    dim3 gfc(1, MM / 128);
    sgemm_bias<128,64,16,8,4><<<gfc, 256>>>(y, fcw, fcb, out, MM, II, HH);
}

// round 4
// speedup vs baseline: 1.3756x; 1.3756x over previous
#include <cuda_runtime.h>
#include <cstdint>

#define BB 64
#define TT 1024
#define II 64
#define HH 512
#define GG 1536
#define MM (BB*TT)

typedef unsigned long long u64;

__device__ float g_xg[(size_t)MM * GG];
__device__ float g_y [(size_t)MM * HH];
__device__ float g_h [2][BB * HH];
__device__ unsigned g_bar4[4];

__device__ __forceinline__ void ffma2(u64 &d, u64 a, u64 b) {
    asm("fma.rn.f32x2 %0,%1,%2,%0;" : "+l"(d) : "l"(a), "l"(b));
}
__device__ __forceinline__ u64 pack2(float x, float y) {
    u64 r; asm("mov.b64 %0,{%1,%2};" : "=l"(r) : "f"(x), "f"(y)); return r;
}
__device__ __forceinline__ float2 unpack2(u64 v) {
    float2 f; asm("mov.b64 {%0,%1},%2;" : "=f"(f.x), "=f"(f.y) : "l"(v)); return f;
}
__device__ __forceinline__ u64 add2(u64 a, u64 b) {
    asm("add.rn.f32x2 %0,%0,%1;" : "+l"(a) : "l"(b)); return a;
}

__global__ void k_zero() {
    int i = blockIdx.x * blockDim.x + threadIdx.x;
    if (i < 4) g_bar4[i] = 0u;
    float* p = &g_h[0][0];
    for (int idx = i; idx < 2 * BB * HH; idx += gridDim.x * blockDim.x) p[idx] = 0.f;
}

// C[M,N] = A[M,K] @ W[N,K]^T + bias, FFMA2 inner loop.
// Thread tile: TM rows (r+16i) x TNP col-pairs (cols 2c+32j, 2c+32j+1).
template <int BM, int BN, int BK, int TM, int TNP>
__global__ __launch_bounds__(256)
void sgemm_bias(const float* __restrict__ A, const float* __restrict__ W,
                const float* __restrict__ bias, float* __restrict__ C,
                int M, int N, int K)
{
    __shared__ u64   As2[BK][BM];   // duplicated {a,a}
    __shared__ float Ws [BK][BN];
    const int tid = threadIdx.x, c = tid & 15, r = tid >> 4;
    const int m0 = blockIdx.y * BM, n0 = blockIdx.x * BN;

    u64 acc[TM][TNP];
#pragma unroll
    for (int i = 0; i < TM; i++)
#pragma unroll
        for (int j = 0; j < TNP; j++) acc[i][j] = 0ull;

    for (int k0 = 0; k0 < K; k0 += BK) {
        for (int i = tid; i < BM * BK / 4; i += 256) {
            int am = i / (BK / 4), ak = (i % (BK / 4)) * 4;
            float4 v = *(const float4*)(A + (size_t)(m0 + am) * K + k0 + ak);
            As2[ak    ][am] = pack2(v.x, v.x);
            As2[ak + 1][am] = pack2(v.y, v.y);
            As2[ak + 2][am] = pack2(v.z, v.z);
            As2[ak + 3][am] = pack2(v.w, v.w);
        }
        for (int i = tid; i < BN * BK / 4; i += 256) {
            int wn = i / (BK / 4), wk = (i % (BK / 4)) * 4;
            float4 v = *(const float4*)(W + (size_t)(n0 + wn) * K + k0 + wk);
            Ws[wk][wn] = v.x; Ws[wk + 1][wn] = v.y;
            Ws[wk + 2][wn] = v.z; Ws[wk + 3][wn] = v.w;
        }
        __syncthreads();
#pragma unroll
        for (int kk = 0; kk < BK; kk++) {
            u64 a2[TM], b2[TNP];
#pragma unroll
            for (int i = 0; i < TM; i++) a2[i] = As2[kk][r + 16 * i];
#pragma unroll
            for (int j = 0; j < TNP; j++) b2[j] = *(const u64*)&Ws[kk][2 * c + 32 * j];
#pragma unroll
            for (int i = 0; i < TM; i++)
#pragma unroll
                for (int j = 0; j < TNP; j++) ffma2(acc[i][j], a2[i], b2[j]);
        }
        __syncthreads();
    }
#pragma unroll
    for (int i = 0; i < TM; i++) {
        int m = m0 + r + 16 * i;
#pragma unroll
        for (int j = 0; j < TNP; j++) {
            int col = n0 + 2 * c + 32 * j;
            u64 res = add2(acc[i][j], *(const u64*)(bias + col));
            *(u64*)(C + (size_t)m * N + col) = res;
        }
    }
}

// Persistent GRU scan, 128 CTAs (4 batch-groups x 32 hidden-slices), 256 thr.
// Thread (jl, ks): hidden unit jhid = hsid*16+jl, K-slice ks (32 k-elems),
// weights in registers; h staged in SMEM; 16-lane shuffle reduction.
__global__ __launch_bounds__(256, 1)
void gru_scan(const float* __restrict__ w_hh, const float* __restrict__ b_hh)
{
    __shared__ float hsm[16 * 514];   // [ks][b*32+kw], 514-stride conflict-free
    const int tid  = threadIdx.x;
    const int hsid = blockIdx.x & 31, bg = blockIdx.x >> 5;
    const int ks   = tid & 15;
    const int jl   = ((tid >> 5) << 1) | ((tid >> 4) & 1);
    const int jhid = hsid * 16 + jl;
    const int bmine = bg * 16 + ks;

    u64 w2r[48];
#pragma unroll
    for (int g = 0; g < 3; g++)
#pragma unroll
        for (int i = 0; i < 16; i++)
            w2r[g * 16 + i] = *(const u64*)(w_hh + (size_t)(g * HH + jhid) * HH + ks * 32 + 2 * i);
    const float bhr = b_hh[jhid], bhz = b_hh[HH + jhid], bhn = b_hh[2 * HH + jhid];

    const int holdIdx = (jhid >> 5) * 514 + ks * 32 + (jhid & 31);
    float2* hs2 = (float2*)hsm;
    const int dstbase = (tid >> 4) * 257 + (tid & 15);
    const float* xgp = g_xg + (size_t)bmine * TT * GG + jhid;
    float* yp = g_y + (size_t)bmine * TT * HH + jhid;
    const int hw = bmine * HH + jhid;

    for (int t = 0; t < TT; t++) {
        float xr = __ldcg(xgp), xz = __ldcg(xgp + HH), xn = __ldcg(xgp + 2 * HH);
        const float2* src = (const float2*)(g_h[t & 1] + bg * 16 * HH);
#pragma unroll
        for (int i = 0; i < 16; i++)
            hs2[dstbase + i * 16] = __ldcg(src + i * 256 + tid);
        __syncthreads();

        const u64* hseg = (const u64*)hsm + ks * 257;
        float hold = hsm[holdIdx];
        float rS = 0.f, zS = 0.f, nS = 0.f;
#pragma unroll 2
        for (int b = 0; b < 16; b++) {
            const u64* hb = hseg + b * 16;
            u64 a0 = 0ull, a1 = 0ull, a2v = 0ull;
#pragma unroll
            for (int i = 0; i < 16; i++) {
                u64 h = hb[i];
                ffma2(a0,  h, w2r[i]);
                ffma2(a1,  h, w2r[16 + i]);
                ffma2(a2v, h, w2r[32 + i]);
            }
            float2 f0 = unpack2(a0), f1 = unpack2(a1), f2 = unpack2(a2v);
            float s0 = f0.x + f0.y, s1 = f1.x + f1.y, s2 = f2.x + f2.y;
#pragma unroll
            for (int s = 1; s < 16; s <<= 1) {
                s0 += __shfl_xor_sync(0xffffffffu, s0, s);
                s1 += __shfl_xor_sync(0xffffffffu, s1, s);
                s2 += __shfl_xor_sync(0xffffffffu, s2, s);
            }
            if (ks == b) { rS = s0; zS = s1; nS = s2; }
        }
        float r = 1.f / (1.f + __expf(-(xr + rS + bhr)));
        float z = 1.f / (1.f + __expf(-(xz + zS + bhz)));
        float n = tanhf(xn + r * (nS + bhn));
        float hnew = (1.f - z) * n + z * hold;
        __stcg(&g_h[(t + 1) & 1][hw], hnew);
        yp[0] = hnew;
        xgp += GG; yp += HH;

        __threadfence();
        __syncthreads();
        if (tid == 0) {
            unsigned tgt = (unsigned)(t + 1) * 32u;
            atomicAdd(&g_bar4[bg], 1u);
            while (*(volatile unsigned*)&g_bar4[bg] < tgt) __nanosleep(20);
        }
        __syncthreads();
    }
}

extern "C" void kernel_launch(void* const* d_in, const int* in_sizes, int n_in,
                              void* d_out, int out_size)
{
    const float* x    = (const float*)d_in[0];
    const float* wih0 = (const float*)d_in[1];
    const float* whh0 = (const float*)d_in[2];
    const float* bih0 = (const float*)d_in[3];
    const float* bhh0 = (const float*)d_in[4];
    const float* wih1 = (const float*)d_in[5];
    const float* whh1 = (const float*)d_in[6];
    const float* bih1 = (const float*)d_in[7];
    const float* bhh1 = (const float*)d_in[8];
    const float* fcw  = (const float*)d_in[9];
    const float* fcb  = (const float*)d_in[10];
    float* out = (float*)d_out;
    (void)in_sizes; (void)n_in; (void)out_size;

    float *xg, *y;
    cudaGetSymbolAddress((void**)&xg, g_xg);
    cudaGetSymbolAddress((void**)&y,  g_y);

    dim3 gxg(GG / 128, MM / 128);

    // layer 0
    sgemm_bias<128,128,16,8,4><<<gxg, 256>>>(x, wih0, bih0, xg, MM, GG, II);
    k_zero<<<64, 256>>>();
    gru_scan<<<128, 256>>>(whh0, bhh0);

    // layer 1
    sgemm_bias<128,128,16,8,4><<<gxg, 256>>>(y, wih1, bih1, xg, MM, GG, HH);
    k_zero<<<64, 256>>>();
    gru_scan<<<128, 256>>>(whh1, bhh1);

    // output FC
    sgemm_bias<128,64,16,8,2><<<dim3(1, MM / 128), 256>>>(y, fcw, fcb, out, MM, II, HH);
}

// round 5
// speedup vs baseline: 1.6099x; 1.1704x over previous
#include <cuda_runtime.h>
#include <cstdint>

#define BB 64
#define TT 1024
#define II 64
#define HH 512
#define GG 1536
#define MM (BB*TT)

typedef unsigned long long u64;

__device__ float g_xg[(size_t)MM * GG];
__device__ float g_y [(size_t)MM * HH];
__device__ float g_h [2][BB * HH];
__device__ unsigned g_bar4[4];

__device__ __forceinline__ void ffma2(u64 &d, u64 a, u64 b) {
    asm("fma.rn.f32x2 %0,%1,%2,%0;" : "+l"(d) : "l"(a), "l"(b));
}
__device__ __forceinline__ u64 pack2(float x, float y) {
    u64 r; asm("mov.b64 %0,{%1,%2};" : "=l"(r) : "f"(x), "f"(y)); return r;
}
__device__ __forceinline__ float2 unpack2(u64 v) {
    float2 f; asm("mov.b64 {%0,%1},%2;" : "=f"(f.x), "=f"(f.y) : "l"(v)); return f;
}
__device__ __forceinline__ u64 add2(u64 a, u64 b) {
    asm("add.rn.f32x2 %0,%0,%1;" : "+l"(a) : "l"(b)); return a;
}

__global__ void k_zero() {
    int i = blockIdx.x * blockDim.x + threadIdx.x;
    if (i < 4) g_bar4[i] = 0u;
    float* p = &g_h[0][0];
    for (int idx = i; idx < 2 * BB * HH; idx += gridDim.x * blockDim.x) p[idx] = 0.f;
}

// C[M,N] = A[M,K] @ W[N,K]^T + bias. FFMA2 inner, double-buffered smem.
template <int BM, int BN, int BK, int TM, int TNP>
__global__ __launch_bounds__(256, 2)
void sgemm_bias(const float* __restrict__ A, const float* __restrict__ W,
                const float* __restrict__ bias, float* __restrict__ C,
                int M, int N, int K)
{
    __shared__ u64   As2[2][BK][BM];
    __shared__ float Ws [2][BK][BN];
    constexpr int NA = BM * BK / 4 / 256;
    constexpr int NW = BN * BK / 4 / 256;
    const int tid = threadIdx.x, c = tid & 15, r = tid >> 4;
    const int m0 = blockIdx.y * BM, n0 = blockIdx.x * BN;

    u64 acc[TM][TNP];
#pragma unroll
    for (int i = 0; i < TM; i++)
#pragma unroll
        for (int j = 0; j < TNP; j++) acc[i][j] = 0ull;

    // prologue: tile 0 -> buffer 0
#pragma unroll
    for (int q = 0; q < NA; q++) {
        int i = tid + q * 256;
        int am = i / (BK / 4), ak = (i % (BK / 4)) * 4;
        float4 v = *(const float4*)(A + (size_t)(m0 + am) * K + ak);
        As2[0][ak][am] = pack2(v.x, v.x); As2[0][ak + 1][am] = pack2(v.y, v.y);
        As2[0][ak + 2][am] = pack2(v.z, v.z); As2[0][ak + 3][am] = pack2(v.w, v.w);
    }
#pragma unroll
    for (int q = 0; q < NW; q++) {
        int i = tid + q * 256;
        int wn = i / (BK / 4), wk = (i % (BK / 4)) * 4;
        float4 v = *(const float4*)(W + (size_t)(n0 + wn) * K + wk);
        Ws[0][wk][wn] = v.x; Ws[0][wk + 1][wn] = v.y;
        Ws[0][wk + 2][wn] = v.z; Ws[0][wk + 3][wn] = v.w;
    }
    __syncthreads();

    int buf = 0;
    for (int k0 = 0; k0 < K; k0 += BK) {
        const int kn = k0 + BK;
        float4 pa[NA], pw[NW];
        if (kn < K) {
#pragma unroll
            for (int q = 0; q < NA; q++) {
                int i = tid + q * 256;
                int am = i / (BK / 4), ak = (i % (BK / 4)) * 4;
                pa[q] = *(const float4*)(A + (size_t)(m0 + am) * K + kn + ak);
            }
#pragma unroll
            for (int q = 0; q < NW; q++) {
                int i = tid + q * 256;
                int wn = i / (BK / 4), wk = (i % (BK / 4)) * 4;
                pw[q] = *(const float4*)(W + (size_t)(n0 + wn) * K + kn + wk);
            }
        }
#pragma unroll
        for (int kk = 0; kk < BK; kk++) {
            u64 a2[TM], b2[TNP];
#pragma unroll
            for (int i = 0; i < TM; i++) a2[i] = As2[buf][kk][r + 16 * i];
#pragma unroll
            for (int j = 0; j < TNP; j++) b2[j] = *(const u64*)&Ws[buf][kk][2 * c + 32 * j];
#pragma unroll
            for (int i = 0; i < TM; i++)
#pragma unroll
                for (int j = 0; j < TNP; j++) ffma2(acc[i][j], a2[i], b2[j]);
        }
        if (kn < K) {
            int nb = buf ^ 1;
#pragma unroll
            for (int q = 0; q < NA; q++) {
                int i = tid + q * 256;
                int am = i / (BK / 4), ak = (i % (BK / 4)) * 4;
                As2[nb][ak][am] = pack2(pa[q].x, pa[q].x);
                As2[nb][ak + 1][am] = pack2(pa[q].y, pa[q].y);
                As2[nb][ak + 2][am] = pack2(pa[q].z, pa[q].z);
                As2[nb][ak + 3][am] = pack2(pa[q].w, pa[q].w);
            }
#pragma unroll
            for (int q = 0; q < NW; q++) {
                int i = tid + q * 256;
                int wn = i / (BK / 4), wk = (i % (BK / 4)) * 4;
                Ws[nb][wk][wn] = pw[q].x; Ws[nb][wk + 1][wn] = pw[q].y;
                Ws[nb][wk + 2][wn] = pw[q].z; Ws[nb][wk + 3][wn] = pw[q].w;
            }
        }
        __syncthreads();
        buf ^= 1;
    }
#pragma unroll
    for (int i = 0; i < TM; i++) {
        int m = m0 + r + 16 * i;
#pragma unroll
        for (int j = 0; j < TNP; j++) {
            int col = n0 + 2 * c + 32 * j;
            u64 res = add2(acc[i][j], *(const u64*)(bias + col));
            *(u64*)(C + (size_t)m * N + col) = res;
        }
    }
}

// Persistent GRU scan: 128 CTAs (4 batch-groups x 32 hidden-slices) x 256 thr.
// Thread (jl, ks): hidden jhid, k-slice ks; weights in regs; reduce-scatter.
__global__ __launch_bounds__(256, 1)
void gru_scan(const float* __restrict__ w_hh, const float* __restrict__ b_hh)
{
    __shared__ float hsm[16 * 514];
    const int tid  = threadIdx.x;
    const int hsid = blockIdx.x & 31, bg = blockIdx.x >> 5;
    const int ks   = tid & 15;
    const int jl   = ((tid >> 5) << 1) | ((tid >> 4) & 1);
    const int jhid = hsid * 16 + jl;
    const int bmine = bg * 16 + ks;

    u64 w2r[48];
#pragma unroll
    for (int g = 0; g < 3; g++)
#pragma unroll
        for (int i = 0; i < 16; i++)
            w2r[g * 16 + i] = *(const u64*)(w_hh + (size_t)(g * HH + jhid) * HH + ks * 32 + 2 * i);
    const float bhr = b_hh[jhid], bhz = b_hh[HH + jhid], bhn = b_hh[2 * HH + jhid];

    const int holdIdx = (jhid >> 5) * 514 + ks * 32 + (jhid & 31);
    float2* hs2 = (float2*)hsm;
    const int dstbase = (tid >> 4) * 257 + (tid & 15);
    const float* xgp = g_xg + (size_t)bmine * TT * GG + jhid;
    float* yp = g_y + (size_t)bmine * TT * HH + jhid;
    const int hw = bmine * HH + jhid;

    float xr = __ldcg(xgp), xz = __ldcg(xgp + HH), xn = __ldcg(xgp + 2 * HH);

    for (int t = 0; t < TT; t++) {
        const float2* src = (const float2*)(g_h[t & 1] + bg * 16 * HH);
#pragma unroll
        for (int i = 0; i < 16; i++)
            hs2[dstbase + i * 16] = __ldcg(src + i * 256 + tid);
        __syncthreads();

        const u64* hseg = (const u64*)hsm + ks * 257;
        float hold = hsm[holdIdx];
        float s0[16], s1[16], s2[16];
#pragma unroll
        for (int b = 0; b < 16; b++) {
            const u64* hb = hseg + b * 16;
            u64 a0 = 0ull, a1 = 0ull, a2v = 0ull;
#pragma unroll
            for (int i = 0; i < 16; i++) {
                u64 h = hb[i];
                ffma2(a0,  h, w2r[i]);
                ffma2(a1,  h, w2r[16 + i]);
                ffma2(a2v, h, w2r[32 + i]);
            }
            float2 f0 = unpack2(a0), f1 = unpack2(a1), f2 = unpack2(a2v);
            s0[b] = f0.x + f0.y; s1[b] = f1.x + f1.y; s2[b] = f2.x + f2.y;
        }
        // recursive-halving reduce-scatter over the 16 k-slice lanes:
        // after round s, s0[i] holds b = (bits of ks above s) + i; ends at s0[0] <-> b = ks.
#pragma unroll
        for (int s = 8; s >= 1; s >>= 1) {
            const bool up = (ks & s) != 0;
#pragma unroll
            for (int i = 0; i < s; i++) {
                float v0 = up ? s0[i] : s0[i + s];
                float v1 = up ? s1[i] : s1[i + s];
                float v2 = up ? s2[i] : s2[i + s];
                v0 = __shfl_xor_sync(0xffffffffu, v0, s);
                v1 = __shfl_xor_sync(0xffffffffu, v1, s);
                v2 = __shfl_xor_sync(0xffffffffu, v2, s);
                s0[i] = (up ? s0[i + s] : s0[i]) + v0;
                s1[i] = (up ? s1[i + s] : s1[i]) + v1;
                s2[i] = (up ? s2[i + s] : s2[i]) + v2;
            }
        }
        float r = 1.f / (1.f + __expf(-(xr + s0[0] + bhr)));
        float z = 1.f / (1.f + __expf(-(xz + s1[0] + bhz)));
        float n = tanhf(xn + r * (s2[0] + bhn));
        float hnew = (1.f - z) * n + z * hold;
        __stcg(&g_h[(t + 1) & 1][hw], hnew);
        yp[0] = hnew;
        xgp += GG; yp += HH;

        // prefetch next step's input gates before the barrier wait
        const float* nx = (t + 1 < TT) ? xgp : g_xg;
        xr = __ldcg(nx); xz = __ldcg(nx + HH); xn = __ldcg(nx + 2 * HH);

        __syncthreads();
        if (tid == 0) {
            __threadfence();
            unsigned tgt = (unsigned)(t + 1) * 32u;
            atomicAdd(&g_bar4[bg], 1u);
            while (*(volatile unsigned*)&g_bar4[bg] < tgt) __nanosleep(20);
        }
        __syncthreads();
    }
}

extern "C" void kernel_launch(void* const* d_in, const int* in_sizes, int n_in,
                              void* d_out, int out_size)
{
    const float* x    = (const float*)d_in[0];
    const float* wih0 = (const float*)d_in[1];
    const float* whh0 = (const float*)d_in[2];
    const float* bih0 = (const float*)d_in[3];
    const float* bhh0 = (const float*)d_in[4];
    const float* wih1 = (const float*)d_in[5];
    const float* whh1 = (const float*)d_in[6];
    const float* bih1 = (const float*)d_in[7];
    const float* bhh1 = (const float*)d_in[8];
    const float* fcw  = (const float*)d_in[9];
    const float* fcb  = (const float*)d_in[10];
    float* out = (float*)d_out;
    (void)in_sizes; (void)n_in; (void)out_size;

    float *xg, *y;
    cudaGetSymbolAddress((void**)&xg, g_xg);
    cudaGetSymbolAddress((void**)&y,  g_y);

    dim3 gxg(GG / 128, MM / 128);

    sgemm_bias<128,128,16,8,4><<<gxg, 256>>>(x, wih0, bih0, xg, MM, GG, II);
    k_zero<<<64, 256>>>();
    gru_scan<<<128, 256>>>(whh0, bhh0);

    sgemm_bias<128,128,16,8,4><<<gxg, 256>>>(y, wih1, bih1, xg, MM, GG, HH);
    k_zero<<<64, 256>>>();
    gru_scan<<<128, 256>>>(whh1, bhh1);

    sgemm_bias<128,64,16,8,2><<<dim3(1, MM / 128), 256>>>(y, fcw, fcb, out, MM, II, HH);
}